// round 3
// baseline (speedup 1.0000x reference)
#include <cuda_runtime.h>
#include <stdint.h>

// Scratch: __device__ globals (no allocation allowed).
#define MAX_N 131072
__device__ int   g_counts[MAX_N];
__device__ float g_penalty[MAX_N];

// Valence table: default 4; {1:1, 6:4, 7:3, 8:2, 9:1, 15:5, 16:6, 17:7}
__device__ __forceinline__ float valence_of(int z) {
    switch (z) {
        case 1:  return 1.0f;
        case 9:  return 1.0f;
        case 7:  return 3.0f;
        case 8:  return 2.0f;
        case 15: return 5.0f;
        case 16: return 6.0f;
        case 17: return 7.0f;
        default: return 4.0f;   // covers 6 and all others
    }
}

// K1: zero the bond-count scratch and the loss output slot.
__global__ void k_zero(int n, float* loss_slot) {
    int i = blockIdx.x * blockDim.x + threadIdx.x;
    if (i < n) g_counts[i] = 0;
    if (i == 0) *loss_slot = 0.0f;
}

// K2: scatter-add bond counts from edge sources (int32 indices).
// Grid-stride, 4 edges/iter via int4 (16B loads).
__global__ void k_count_edges(const int* __restrict__ row, int nquads, int E) {
    int stride = gridDim.x * blockDim.x;
    for (int i = blockIdx.x * blockDim.x + threadIdx.x; i < nquads; i += stride) {
        int4 e = reinterpret_cast<const int4*>(row)[i];
        atomicAdd(&g_counts[e.x], 1);
        atomicAdd(&g_counts[e.y], 1);
        atomicAdd(&g_counts[e.z], 1);
        atomicAdd(&g_counts[e.w], 1);
    }
    // tail: E % 4 edges
    if (blockIdx.x == 0 && threadIdx.x < (E & 3)) {
        atomicAdd(&g_counts[row[nquads * 4 + threadIdx.x]], 1);
    }
}

// K3: per-atom violation -> penalty array; warp-reduced loss into d_out slot.
__global__ void k_penalty_loss(const int* __restrict__ atom_types,
                               int n, float loss_scale, float* loss_slot) {
    int i = blockIdx.x * blockDim.x + threadIdx.x;
    float viol = 0.0f;
    if (i < n) {
        float v = (float)g_counts[i] - valence_of(atom_types[i]);
        viol = fmaxf(v, 0.0f);
        g_penalty[i] = (viol > 0.0f) ? (1.0f - 0.1f * viol) : 1.0f;
    }
    // warp reduce
    #pragma unroll
    for (int off = 16; off > 0; off >>= 1)
        viol += __shfl_down_sync(0xFFFFFFFFu, viol, off);
    if ((threadIdx.x & 31) == 0 && viol != 0.0f)
        atomicAdd(loss_slot, viol * loss_scale);
}

// K4: h_new = h * penalty[row], float4 vectorized, grid-stride.
// Dominant pass (~205 MB read+write).
__global__ void k_scale_h(const float4* __restrict__ h, float4* __restrict__ out,
                          int total4, int d4, int shift) {
    int stride = gridDim.x * blockDim.x;
    for (int idx = blockIdx.x * blockDim.x + threadIdx.x; idx < total4; idx += stride) {
        int row = (shift >= 0) ? (idx >> shift) : (idx / d4);
        float p = g_penalty[row];
        float4 v = h[idx];
        v.x *= p; v.y *= p; v.z *= p; v.w *= p;
        out[idx] = v;
    }
}

extern "C" void kernel_launch(void* const* d_in, const int* in_sizes, int n_in,
                              void* d_out, int out_size) {
    const float* h     = (const float*)d_in[0];
    const int*   edges = (const int*)d_in[1];   // [2, E] int32; row = edges[0..E)
    const int*   types = (const int*)d_in[2];   // [N] int32
    float* out = (float*)d_out;

    const int N = in_sizes[2];
    const int E = in_sizes[1] / 2;
    const int D = in_sizes[0] / N;

    float* loss_slot = out + (out_size - 1);

    // K1: zero scratch + loss
    {
        int threads = 256, blocks = (N + threads - 1) / threads;
        k_zero<<<blocks, threads>>>(N, loss_slot);
    }
    // K2: edge scatter (int32 row indices, 4 per int4)
    {
        int nquads = E / 4;
        int threads = 256;
        int blocks = (nquads + threads - 1) / threads;
        if (blocks < 1) blocks = 1;
        if (blocks > 8192) blocks = 8192;
        k_count_edges<<<blocks, threads>>>(edges, nquads, E);
    }
    // K3: penalty + loss (mean * CONSTRAINT_WEIGHT)
    {
        float loss_scale = 0.05f / (float)N;
        int threads = 256, blocks = (N + threads - 1) / threads;
        k_penalty_loss<<<blocks, threads>>>(types, N, loss_scale, loss_slot);
    }
    // K4: scale features
    {
        int d4 = D / 4;
        int shift = -1;
        if (d4 > 0 && (d4 & (d4 - 1)) == 0) {
            shift = 0;
            while ((1 << shift) != d4) shift++;
        }
        int total4 = (int)((long long)N * D / 4);
        int threads = 256;
        int blocks = (total4 + threads - 1) / threads;
        if (blocks < 1) blocks = 1;
        if (blocks > 65535) blocks = 65535;
        k_scale_h<<<blocks, threads>>>((const float4*)h, (float4*)out,
                                       total4, d4, shift);
    }
}

// round 5
// speedup vs baseline: 1.0683x; 1.0683x over previous
#include <cuda_runtime.h>
#include <stdint.h>

// Scratch: __device__ globals (no allocation allowed).
#define MAX_N 131072
__device__ int g_counts[MAX_N];

// Valence table: default 4; {1:1, 6:4, 7:3, 8:2, 9:1, 15:5, 16:6, 17:7}
__device__ __forceinline__ float valence_of(int z) {
    switch (z) {
        case 1:  return 1.0f;
        case 9:  return 1.0f;
        case 7:  return 3.0f;
        case 8:  return 2.0f;
        case 15: return 5.0f;
        case 16: return 6.0f;
        case 17: return 7.0f;
        default: return 4.0f;   // covers 6 and all others
    }
}

// K1: zero the bond-count scratch and the loss output slot.
__global__ void k_zero(int n, float* loss_slot) {
    int i = blockIdx.x * blockDim.x + threadIdx.x;
    if (i < n) g_counts[i] = 0;
    if (i == 0) *loss_slot = 0.0f;
}

// K2: scatter-add bond counts from edge sources (int32 indices).
// One int4 (4 edges) per thread; atomics compile to RED (no return).
__global__ void k_count_edges(const int* __restrict__ row, int nquads, int E) {
    int stride = gridDim.x * blockDim.x;
    for (int i = blockIdx.x * blockDim.x + threadIdx.x; i < nquads; i += stride) {
        int4 e = reinterpret_cast<const int4*>(row)[i];
        atomicAdd(&g_counts[e.x], 1);
        atomicAdd(&g_counts[e.y], 1);
        atomicAdd(&g_counts[e.z], 1);
        atomicAdd(&g_counts[e.w], 1);
    }
    // tail: E % 4 edges
    if (blockIdx.x == 0 && threadIdx.x < (E & 3)) {
        atomicAdd(&g_counts[row[nquads * 4 + threadIdx.x]], 1);
    }
}

// K3 (fused): warp-per-row penalty compute + feature scale + loss reduce.
// Dominant pass (~205 MB read+write), streaming cache hints (h/out touched once).
__global__ void k_penalty_scale(const float4* __restrict__ h, float4* __restrict__ out,
                                const int* __restrict__ types,
                                int n_rows, int d4, float loss_scale,
                                float* loss_slot) {
    __shared__ float s_part[32];
    const int lane  = threadIdx.x & 31;
    const int warp  = threadIdx.x >> 5;
    const int gwarp = (blockIdx.x * blockDim.x + threadIdx.x) >> 5;
    const int nwarp = (gridDim.x * blockDim.x) >> 5;

    float acc = 0.0f;
    for (int row = gwarp; row < n_rows; row += nwarp) {
        float p = 1.0f;
        if (lane == 0) {
            float viol = fmaxf((float)g_counts[row] - valence_of(types[row]), 0.0f);
            acc += viol;
            p = (viol > 0.0f) ? (1.0f - 0.1f * viol) : 1.0f;
        }
        p = __shfl_sync(0xFFFFFFFFu, p, 0);

        const float4* hrow = h   + (size_t)row * d4;
        float4*       orow = out + (size_t)row * d4;
        if (d4 == 64) {
            // D=256 fast path: 2 independent 16B loads before stores (MLP=2).
            float4 a = __ldcs(hrow + lane);
            float4 b = __ldcs(hrow + lane + 32);
            a.x *= p; a.y *= p; a.z *= p; a.w *= p;
            b.x *= p; b.y *= p; b.z *= p; b.w *= p;
            __stcs(orow + lane, a);
            __stcs(orow + lane + 32, b);
        } else {
            for (int c = lane; c < d4; c += 32) {
                float4 v = __ldcs(hrow + c);
                v.x *= p; v.y *= p; v.z *= p; v.w *= p;
                __stcs(orow + c, v);
            }
        }
    }

    // loss reduce: acc lives only in lane 0 of each warp.
    if (lane == 0) s_part[warp] = acc;
    __syncthreads();
    if (threadIdx.x == 0) {
        float s = 0.0f;
        int nw = blockDim.x >> 5;
        for (int w = 0; w < nw; w++) s += s_part[w];
        if (s != 0.0f) atomicAdd(loss_slot, s * loss_scale);
    }
}

extern "C" void kernel_launch(void* const* d_in, const int* in_sizes, int n_in,
                              void* d_out, int out_size) {
    const float* h     = (const float*)d_in[0];
    const int*   edges = (const int*)d_in[1];   // [2, E] int32; row = edges[0..E)
    const int*   types = (const int*)d_in[2];   // [N] int32
    float* out = (float*)d_out;

    const int N = in_sizes[2];
    const int E = in_sizes[1] / 2;
    const int D = in_sizes[0] / N;

    float* loss_slot = out + (out_size - 1);

    // K1: zero scratch + loss
    {
        int threads = 256, blocks = (N + threads - 1) / threads;
        k_zero<<<blocks, threads>>>(N, loss_slot);
    }
    // K2: edge scatter (4 int32 indices per int4)
    {
        int nquads = E / 4;
        int threads = 256;
        int blocks = (nquads + threads - 1) / threads;
        if (blocks < 1) blocks = 1;
        if (blocks > 8192) blocks = 8192;
        k_count_edges<<<blocks, threads>>>(edges, nquads, E);
    }
    // K3: fused penalty + loss + scale
    {
        float loss_scale = 0.05f / (float)N;
        int d4 = D / 4;
        int threads = 256;
        // 8 warps/block; ~full occupancy over 148 SMs, grid-stride over rows.
        int blocks = 148 * 8;
        int need = (N + 7) / 8;          // one row per warp minimum
        if (blocks > need) blocks = need;
        if (blocks < 1) blocks = 1;
        k_penalty_scale<<<blocks, threads>>>((const float4*)h, (float4*)out,
                                             types, N, d4, loss_scale, loss_slot);
    }
}